// round 10
// baseline (speedup 1.0000x reference)
#include <cuda_runtime.h>
#include <stdint.h>

#define NN 50000
#define NE 800000
#define IN_DIM 96
#define HID 32
#define OUT_DIM 64
#define EPT 4   // edges per thread in scatter (MLP)

// ---------------- scratch (device globals; no allocation allowed) ----------
__device__ __align__(16) float g_y1[NN * HID];    // x @ W1l   (to be aggregated)
__device__ __align__(16) float g_agg1[NN * HID];  // scatter accum, layer 1
__device__ __align__(16) float g_h[NN * HID];     // hidden activations
__device__ __align__(16) float g_agg2[NN * HID];  // scatter accum, layer 2
__device__ float g_cnt[NN];
__device__ float g_invc[NN];

// ---------------- zero the accumulators (coalesced, proven) ----------------
__global__ void zero_bufs() {
    int i = blockIdx.x * blockDim.x + threadIdx.x;
    const int nv4 = NN * HID / 4;
    if (i < nv4) {
        ((float4*)g_agg1)[i] = make_float4(0.f, 0.f, 0.f, 0.f);
        ((float4*)g_agg2)[i] = make_float4(0.f, 0.f, 0.f, 0.f);
    }
    if (i < NN) g_cnt[i] = 0.f;
}

// ---------------- gemm_y: y1 = x @ W1l (32 accumulators) -------------------
__global__ void __launch_bounds__(128) gemm_y_kernel(
    const float* __restrict__ x,
    const float* __restrict__ W1l,
    int n)
{
    __shared__ float sW[IN_DIM][HID];  // 12 KB
    for (int i = threadIdx.x; i < IN_DIM * HID; i += blockDim.x)
        sW[i / HID][i % HID] = W1l[i];
    __syncthreads();

    int node = blockIdx.x * blockDim.x + threadIdx.x;
    if (node >= n) return;

    float acc[32];
#pragma unroll
    for (int j = 0; j < 32; j++) acc[j] = 0.f;

    const float4* xr = (const float4*)(x + (size_t)node * IN_DIM);
#pragma unroll 1
    for (int kq = 0; kq < IN_DIM / 4; kq++) {
        float4 xv = __ldg(&xr[kq]);
        float xs[4] = {xv.x, xv.y, xv.z, xv.w};
#pragma unroll
        for (int kk = 0; kk < 4; kk++) {
            float xk = xs[kk];
            const float* wr = sW[kq * 4 + kk];
#pragma unroll
            for (int j = 0; j < 32; j += 4) {
                float4 w = *(const float4*)&wr[j];
                acc[j + 0] += xk * w.x;
                acc[j + 1] += xk * w.y;
                acc[j + 2] += xk * w.z;
                acc[j + 3] += xk * w.w;
            }
        }
    }

    float* y = g_y1 + (size_t)node * HID;
#pragma unroll
    for (int j = 0; j < HID; j += 4)
        *(float4*)&y[j] = make_float4(acc[j], acc[j + 1], acc[j + 2], acc[j + 3]);
}

// ---------------- edge scatter: agg[dst] += feat[src] (dim 32) -------------
// 8 threads per edge lane, EPT independent edges per thread.
__global__ void __launch_bounds__(256) scatter_kernel(
    const int* __restrict__ ei, int E, int layer)
{
    int tid = blockIdx.x * blockDim.x + threadIdx.x;
    int g = tid >> 3;           // edge-group id
    int l = tid & 7;            // lane within edge (feature quad)
    int G = (E + EPT - 1) / EPT;
    if (g >= G) return;

    const float* feat = (layer == 0) ? g_y1 : g_h;
    float*       agg  = (layer == 0) ? g_agg1 : g_agg2;

    int  e[EPT];
    bool valid[EPT];
    int  src[EPT], dst[EPT];
#pragma unroll
    for (int k = 0; k < EPT; k++) {
        e[k] = g + k * G;
        valid[k] = (e[k] < E);
    }
#pragma unroll
    for (int k = 0; k < EPT; k++) {
        if (valid[k]) {
            src[k] = __ldg(&ei[e[k]]);
            dst[k] = __ldg(&ei[E + e[k]]);
        }
    }
    float4 v[EPT];
#pragma unroll
    for (int k = 0; k < EPT; k++) {
        if (valid[k])
            v[k] = *(const float4*)(feat + (size_t)src[k] * HID + l * 4);
    }
#pragma unroll
    for (int k = 0; k < EPT; k++) {
        if (valid[k]) {
            float* p = agg + (size_t)dst[k] * HID + l * 4;
            asm volatile("red.global.add.v4.f32 [%0], {%1,%2,%3,%4};"
                         :: "l"(p), "f"(v[k].x), "f"(v[k].y), "f"(v[k].z), "f"(v[k].w)
                         : "memory");
            if (layer == 0 && l == 0) atomicAdd(g_cnt + dst[k], 1.0f);
        }
    }
}

// ------- gemmz_combine: h = relu(agg1/cnt + x@W1r + b1)  (z never stored) ---
__global__ void __launch_bounds__(128) gemmz_combine_kernel(
    const float* __restrict__ x,
    const float* __restrict__ W1r,
    const float* __restrict__ b1,
    int n)
{
    __shared__ float sW[IN_DIM][HID];  // 12 KB
    __shared__ float sB[HID];
    for (int i = threadIdx.x; i < IN_DIM * HID; i += blockDim.x)
        sW[i / HID][i % HID] = W1r[i];
    if (threadIdx.x < HID) sB[threadIdx.x] = b1[threadIdx.x];
    __syncthreads();

    int node = blockIdx.x * blockDim.x + threadIdx.x;
    if (node >= n) return;

    float acc[32];
#pragma unroll
    for (int j = 0; j < 32; j++) acc[j] = 0.f;

    const float4* xr = (const float4*)(x + (size_t)node * IN_DIM);
#pragma unroll 1
    for (int kq = 0; kq < IN_DIM / 4; kq++) {
        float4 xv = __ldg(&xr[kq]);
        float xs[4] = {xv.x, xv.y, xv.z, xv.w};
#pragma unroll
        for (int kk = 0; kk < 4; kk++) {
            float xk = xs[kk];
            const float* wr = sW[kq * 4 + kk];
#pragma unroll
            for (int j = 0; j < 32; j += 4) {
                float4 w = *(const float4*)&wr[j];
                acc[j + 0] += xk * w.x;
                acc[j + 1] += xk * w.y;
                acc[j + 2] += xk * w.z;
                acc[j + 3] += xk * w.w;
            }
        }
    }

    float c = g_cnt[node];
    float invc = 1.0f / fmaxf(c, 1.0f);
    g_invc[node] = invc;

    float* hrow = g_h + (size_t)node * HID;
    const float4* arow = (const float4*)(g_agg1 + (size_t)node * HID);
#pragma unroll
    for (int q = 0; q < 8; q++) {
        float4 a = arow[q];
        float4 h;
        h.x = fmaxf(fmaf(a.x, invc, acc[q * 4 + 0] + sB[q * 4 + 0]), 0.f);
        h.y = fmaxf(fmaf(a.y, invc, acc[q * 4 + 1] + sB[q * 4 + 1]), 0.f);
        h.z = fmaxf(fmaf(a.z, invc, acc[q * 4 + 2] + sB[q * 4 + 2]), 0.f);
        h.w = fmaxf(fmaf(a.w, invc, acc[q * 4 + 3] + sB[q * 4 + 3]), 0.f);
        *(float4*)&hrow[q * 4] = h;
    }
}

// ---------------- layer 2: out = (agg2/cnt)@W2l + h@W2r + b2 ---------------
__global__ void __launch_bounds__(128) layer2_kernel(
    const float* __restrict__ W2l,
    const float* __restrict__ W2r,
    const float* __restrict__ b2,
    float* __restrict__ out,
    int n)
{
    __shared__ float sW[2 * HID][OUT_DIM];  // 16 KB; rows 0..31 = W2l
    for (int i = threadIdx.x; i < HID * OUT_DIM; i += blockDim.x) {
        int k = i / OUT_DIM, j = i % OUT_DIM;
        sW[k][j]       = W2l[i];
        sW[k + HID][j] = W2r[i];
    }
    __syncthreads();

    int node = blockIdx.x * blockDim.x + threadIdx.x;
    if (node >= n) return;

    float invc = g_invc[node];
    float v[64];
#pragma unroll
    for (int k = 0; k < HID; k += 4) {
        float4 a = *(const float4*)&g_agg2[(size_t)node * HID + k];
        v[k + 0] = a.x * invc;
        v[k + 1] = a.y * invc;
        v[k + 2] = a.z * invc;
        v[k + 3] = a.w * invc;
        float4 hh = *(const float4*)&g_h[(size_t)node * HID + k];
        v[HID + k + 0] = hh.x;
        v[HID + k + 1] = hh.y;
        v[HID + k + 2] = hh.z;
        v[HID + k + 3] = hh.w;
    }

#pragma unroll 1
    for (int j = 0; j < OUT_DIM; j += 4) {
        float4 bb = *(const float4*)&b2[j];
        float a0 = bb.x, a1 = bb.y, a2 = bb.z, a3 = bb.w;
#pragma unroll
        for (int k = 0; k < 64; k++) {
            float4 w = *(const float4*)&sW[k][j];
            a0 += v[k] * w.x;
            a1 += v[k] * w.y;
            a2 += v[k] * w.z;
            a3 += v[k] * w.w;
        }
        *(float4*)&out[(size_t)node * OUT_DIM + j] = make_float4(a0, a1, a2, a3);
    }
}

// ---------------- launch --------------------------------------------------
extern "C" void kernel_launch(void* const* d_in, const int* in_sizes, int n_in,
                              void* d_out, int out_size)
{
    const float* x   = (const float*)d_in[0];
    const int*   ei  = (const int*)d_in[1];   // int32 (JAX x64 disabled)
    const float* W1l = (const float*)d_in[2];
    const float* W1r = (const float*)d_in[3];
    const float* b1  = (const float*)d_in[4];
    const float* W2l = (const float*)d_in[5];
    const float* W2r = (const float*)d_in[6];
    const float* b2  = (const float*)d_in[7];
    float*       out = (float*)d_out;

    int n = in_sizes[0] / IN_DIM;   // 50000
    int E = in_sizes[1] / 2;        // 800000

    // 1) zero accumulators + counts
    {
        int tot = NN * HID / 4;
        zero_bufs<<<(tot + 255) / 256, 256>>>();
    }
    // 2) y1 = x@W1l (only what scatter1 needs)
    gemm_y_kernel<<<(n + 127) / 128, 128>>>(x, W1l, n);
    // 3) scatter y1 into agg1 (+ degree counts)
    {
        int G = (E + EPT - 1) / EPT;
        long long work = (long long)G * 8;
        scatter_kernel<<<(int)((work + 255) / 256), 256>>>(ei, E, 0);
    }
    // 4) h = relu(agg1/cnt + x@W1r + b1)   -- z never hits memory
    gemmz_combine_kernel<<<(n + 127) / 128, 128>>>(x, W1r, b1, n);
    // 5) scatter h into agg2
    {
        int G = (E + EPT - 1) / EPT;
        long long work = (long long)G * 8;
        scatter_kernel<<<(int)((work + 255) / 256), 256>>>(ei, E, 1);
    }
    // 6) out = (agg2/cnt)@W2l + h@W2r + b2
    layer2_kernel<<<(n + 127) / 128, 128>>>(W2l, W2r, b2, out, n);
}